// round 15
// baseline (speedup 1.0000x reference)
#include <cuda_runtime.h>
#include <cuda_bf16.h>
#include <cstdint>
#include <math.h>

#define DI __device__ __forceinline__

#define BATCH 64
#define L     1024
#define DDIM  64
#define BM    32
#define NTHR  256
#define SK    72            // Q smem row stride (halves)

// smem byte offsets — 42624 B total => 2 CTAs/SM
#define SM_QHI  0           // 32*144 = 4608
#define SM_QLO  4608
#define SM_OP   9216        // 8 warps x 16 x 64 floats = 32768
#define SM_RED  41984       // float[32][4]
#define SM_IL   42496       // float[32]
#define SM_TOT  42624

DI uint32_t smem_u32(const void* p){ uint32_t a;
  asm("{ .reg .u64 t; cvta.to.shared.u64 t, %1; cvt.u32.u64 %0, t; }":"=r"(a):"l"(p)); return a; }

DI void split2(float x, float y, uint32_t& hi, uint32_t& lo){
  __nv_bfloat16 hx = __float2bfloat16_rn(x), hy = __float2bfloat16_rn(y);
  float rx = x - __bfloat162float(hx), ry = y - __bfloat162float(hy);
  __nv_bfloat162 H; H.x = hx; H.y = hy;
  __nv_bfloat162 L2 = __floats2bfloat162_rn(rx, ry);
  hi = *reinterpret_cast<uint32_t*>(&H);
  lo = *reinterpret_cast<uint32_t*>(&L2);
}

DI void ldmx4(uint32_t* r, uint32_t addr){
  asm volatile("ldmatrix.sync.aligned.m8n8.x4.shared.b16 {%0,%1,%2,%3}, [%4];"
    : "=r"(r[0]),"=r"(r[1]),"=r"(r[2]),"=r"(r[3]) : "r"(addr));
}
DI void mma16816(float* c, const uint32_t* a, uint32_t b0, uint32_t b1){
  asm volatile("mma.sync.aligned.m16n8k16.row.col.f32.bf16.bf16.f32 "
    "{%0,%1,%2,%3}, {%4,%5,%6,%7}, {%8,%9}, {%0,%1,%2,%3};"
    : "+f"(c[0]),"+f"(c[1]),"+f"(c[2]),"+f"(c[3])
    : "r"(a[0]),"r"(a[1]),"r"(a[2]),"r"(a[3]), "r"(b0),"r"(b1));
}

__global__ void __launch_bounds__(NTHR, 2)
sdpa_mma_kernel(const float* __restrict__ q, const float* __restrict__ k,
                const float* __restrict__ v, const int* __restrict__ mask,
                float* __restrict__ out, float* __restrict__ attn)
{
    extern __shared__ char sm[];
    const uint32_t smb = smem_u32(sm);
    float* RED   = (float*)(sm + SM_RED);
    float* ILrow = (float*)(sm + SM_IL);

    const int tid  = threadIdx.x;
    const int wid  = tid >> 5, lane = tid & 31;
    const int wr   = wid >> 2, wc = wid & 3;    // 2 x 4 warp grid
    const int g    = lane >> 3, l7 = lane & 7;
    const int l4   = lane >> 2, q2 = (lane & 3) * 2;
    const int b    = blockIdx.x >> 5;
    const int q0   = (blockIdx.x & 31) * BM;

    // ---- stage Q (pre-scaled 1/8) as bf16 hi/lo ----
    const float* Qg = q + ((size_t)(b * L + q0)) * DDIM;
    #pragma unroll
    for (int j = 0; j < 4; ++j) {
        int id = tid + j * NTHR;              // 1024 float2
        int r = id >> 5, c = (id & 31) * 2;
        float2 x = *(const float2*)&Qg[r * DDIM + c];
        uint32_t hi, lo; split2(x.x * 0.125f, x.y * 0.125f, hi, lo);
        *(uint32_t*)(sm + SM_QHI + r * (SK*2) + c*2) = hi;
        *(uint32_t*)(sm + SM_QLO + r * (SK*2) + c*2) = lo;
    }
    __syncthreads();

    // ---- preload Q A-fragments (resident for whole loop) ----
    uint32_t aH[4][4], aL[4][4];
    {
        int arow = wr*16 + l7 + (g & 1) * 8;
        int akoff = (g >> 1) * 8;
        #pragma unroll
        for (int ks = 0; ks < 4; ++ks) {
            uint32_t off = (uint32_t)(arow * SK + ks*16 + akoff) * 2;
            ldmx4(aH[ks], smb + SM_QHI + off);
            ldmx4(aL[ks], smb + SM_QLO + off);
        }
    }

    float lsumA = 0.f, lsumB = 0.f;
    const float* Kg = k + (size_t)b * L * DDIM;
    const float* Vg = v + (size_t)b * L * DDIM;
    const int rowA = wr * 16 + (lane >> 2);
    const int rowB = rowA + 8;
    const size_t grA = (size_t)(b*L + q0 + rowA) * L;
    const size_t grB = (size_t)(b*L + q0 + rowB) * L;
    float* Ab = attn + ((size_t)(b * L + q0)) * L;

    // O accumulator: warp's 16-key-slice partial, 16 q x 64 d
    float o[8][4];
    #pragma unroll
    for (int f = 0; f < 8; ++f)
        #pragma unroll
        for (int jj = 0; jj < 4; ++jj) o[f][jj] = 0.f;

    // ============ fused loop, NO in-loop barriers: operands direct from global ============
    #pragma unroll 1
    for (int kt = 0; kt < 16; ++kt) {
        const int key0 = kt*64 + wc*16;      // this warp's 16-key slice

        // mask for this tile (latency hidden behind MMA stream)
        int2 cmA[2], cmB[2];
        #pragma unroll
        for (int nf = 0; nf < 2; ++nf) {
            int col = key0 + nf*8 + q2;
            cmA[nf] = *(const int2*)&mask[grA + col];
            cmB[nf] = *(const int2*)&mask[grB + col];
        }

        // ---- GEMM1: S slice = (Q/8) K^T ; K B-frags straight from global ----
        float c4[2][4];
        #pragma unroll
        for (int i = 0; i < 2; ++i)
            #pragma unroll
            for (int jj = 0; jj < 4; ++jj) c4[i][jj] = 0.f;

        #pragma unroll
        for (int ks = 0; ks < 4; ++ks) {
            const float* Kr = Kg + (size_t)(key0 + l4) * DDIM + ks*16 + q2;
            float2 f0 = *(const float2*)(Kr);
            float2 f1 = *(const float2*)(Kr + 8);
            float2 f2 = *(const float2*)(Kr + 8*DDIM);
            float2 f3 = *(const float2*)(Kr + 8*DDIM + 8);
            uint32_t bh[4], bl[4];
            split2(f0.x, f0.y, bh[0], bl[0]);
            split2(f1.x, f1.y, bh[1], bl[1]);
            split2(f2.x, f2.y, bh[2], bl[2]);
            split2(f3.x, f3.y, bh[3], bl[3]);
            mma16816(c4[0], aH[ks], bh[0], bh[1]);
            mma16816(c4[0], aL[ks], bh[0], bh[1]);
            mma16816(c4[0], aH[ks], bl[0], bl[1]);
            mma16816(c4[1], aH[ks], bh[2], bh[3]);
            mma16816(c4[1], aL[ks], bh[2], bh[3]);
            mma16816(c4[1], aH[ks], bl[2], bl[3]);
        }

        // ---- epilogue: e = exp(masked s); write e to attn; pack e as PV A-frags ----
        uint32_t eH[4], eL[4];
        #pragma unroll
        for (int nf = 0; nf < 2; ++nf) {
            int col = key0 + nf*8 + q2;
            float e0 = cmA[nf].x ? 0.f : __expf(c4[nf][0]);
            float e1 = cmA[nf].y ? 0.f : __expf(c4[nf][1]);
            float e2 = cmB[nf].x ? 0.f : __expf(c4[nf][2]);
            float e3 = cmB[nf].y ? 0.f : __expf(c4[nf][3]);
            lsumA += e0 + e1;
            lsumB += e2 + e3;
            *(float2*)&attn[grA + col] = make_float2(e0, e1);
            *(float2*)&attn[grB + col] = make_float2(e2, e3);
            split2(e0, e1, eH[nf*2 + 0], eL[nf*2 + 0]);
            split2(e2, e3, eH[nf*2 + 1], eL[nf*2 + 1]);
        }

        // ---- GEMM2: O += e_slice * V_slice ; V B-frags straight from global ----
        #pragma unroll
        for (int nb = 0; nb < 4; ++nb) {
            const float* Vb = Vg + (size_t)(key0 + q2) * DDIM + nb*16 + l4;
            float v00 = Vb[0];
            float v01 = Vb[DDIM];
            float v10 = Vb[8*DDIM];
            float v11 = Vb[9*DDIM];
            float v20 = Vb[8];
            float v21 = Vb[DDIM + 8];
            float v30 = Vb[8*DDIM + 8];
            float v31 = Vb[9*DDIM + 8];
            uint32_t vh[4], vl[4];
            split2(v00, v01, vh[0], vl[0]);
            split2(v10, v11, vh[1], vl[1]);
            split2(v20, v21, vh[2], vl[2]);
            split2(v30, v31, vh[3], vl[3]);
            mma16816(o[2*nb],   eH, vh[0], vh[1]);
            mma16816(o[2*nb],   eL, vh[0], vh[1]);
            mma16816(o[2*nb],   eH, vl[0], vl[1]);
            mma16816(o[2*nb+1], eH, vh[2], vh[3]);
            mma16816(o[2*nb+1], eL, vh[2], vh[3]);
            mma16816(o[2*nb+1], eH, vl[2], vl[3]);
        }
    }

    // ---- row-sum partials + O partials to smem ----
    lsumA += __shfl_xor_sync(0xffffffffu, lsumA, 1);
    lsumA += __shfl_xor_sync(0xffffffffu, lsumA, 2);
    lsumB += __shfl_xor_sync(0xffffffffu, lsumB, 1);
    lsumB += __shfl_xor_sync(0xffffffffu, lsumB, 2);
    if ((lane & 3) == 0) {
        RED[rowA*4 + wc] = lsumA;
        RED[rowB*4 + wc] = lsumB;
    }
    {
        float* OPw = (float*)(sm + SM_OP) + wid * 16 * 64;
        int r0 = lane >> 2;
        #pragma unroll
        for (int f = 0; f < 8; ++f) {
            int c = f*8 + (lane & 3)*2;
            *(float2*)&OPw[r0*64 + c]      = make_float2(o[f][0], o[f][1]);
            *(float2*)&OPw[(r0+8)*64 + c]  = make_float2(o[f][2], o[f][3]);
        }
    }
    __syncthreads();
    if (tid < 32) {
        float s4 = RED[tid*4] + RED[tid*4+1] + RED[tid*4+2] + RED[tid*4+3];
        ILrow[tid] = 1.f / s4;
    }
    __syncthreads();

    // ---- finalize O: sum 4 key-slice partials, scale by 1/l ----
    {
        int r = tid >> 3, cg = (tid & 7) * 8;
        float il = ILrow[r];
        const float* OP = (const float*)(sm + SM_OP);
        float a0=0,a1=0,a2=0,a3=0,a4=0,a5=0,a6=0,a7=0;
        #pragma unroll
        for (int wcx = 0; wcx < 4; ++wcx) {
            int base = (((r >> 4)*4 + wcx)*16 + (r & 15))*64 + cg;
            float4 u0 = *(const float4*)&OP[base];
            float4 u1 = *(const float4*)&OP[base + 4];
            a0 += u0.x; a1 += u0.y; a2 += u0.z; a3 += u0.w;
            a4 += u1.x; a5 += u1.y; a6 += u1.z; a7 += u1.w;
        }
        float* orow = out + ((size_t)(b*L + q0 + r)) * DDIM + cg;
        *(float4*)&orow[0] = make_float4(a0*il, a1*il, a2*il, a3*il);
        *(float4*)&orow[4] = make_float4(a4*il, a5*il, a6*il, a7*il);
    }

    // ---- streaming attn rescale: p = e * il ----
    #pragma unroll 4
    for (int j = 0; j < 32; ++j) {
        int id = tid + j * NTHR;             // 8192 float4 over 32x1024
        int r = id >> 8, ci = (id & 255) * 4;
        float il = ILrow[r];
        float4 t = *(const float4*)&Ab[(size_t)r * L + ci];
        t.x *= il; t.y *= il; t.z *= il; t.w *= il;
        *(float4*)&Ab[(size_t)r * L + ci] = t;
    }
}

extern "C" void kernel_launch(void* const* d_in, const int* in_sizes, int n_in,
                              void* d_out, int out_size)
{
    (void)in_sizes; (void)n_in; (void)out_size;
    const float* q = (const float*)d_in[0];
    const float* k = (const float*)d_in[1];
    const float* v = (const float*)d_in[2];
    const int*   mask = (const int*)d_in[3];

    float* outp = (float*)d_out;                            // [B, LQ, DD]
    float* attn = outp + (size_t)BATCH * L * DDIM;          // [B, LQ, LK]

    cudaFuncSetAttribute(sdpa_mma_kernel,
                         cudaFuncAttributeMaxDynamicSharedMemorySize, SM_TOT);

    dim3 grid(BATCH * (L / BM));    // 2048
    sdpa_mma_kernel<<<grid, NTHR, SM_TOT>>>(q, k, v, mask, outp, attn);
}

// round 16
// speedup vs baseline: 1.3501x; 1.3501x over previous
#include <cuda_runtime.h>
#include <cuda_bf16.h>
#include <cstdint>
#include <math.h>

#define DI __device__ __forceinline__

#define BATCH 64
#define L     1024
#define DDIM  64
#define BM    32
#define NTHR  256
#define SK    72            // smem row stride (halves)

// smem byte offsets — 83584 B total => 2 CTAs/SM
#define SM_QHI  0           // 32*144 = 4608
#define SM_QLO  4608
#define SM_KV   9216        // 2 buffers x 36864 (KHI/KLO/VHI/VLO @ 0/9216/18432/27648)
#define KVBUF   36864
#define KHI     0
#define KLO     9216
#define VHI     18432
#define VLO     27648
#define SM_OP   9216        // reused AFTER loop (+sync): 8 warps x 16 x 64 floats = 32768
#define SM_RED  82944       // float[32][4]
#define SM_IL   83456       // float[32]
#define SM_TOT  83584

DI uint32_t smem_u32(const void* p){ uint32_t a;
  asm("{ .reg .u64 t; cvta.to.shared.u64 t, %1; cvt.u32.u64 %0, t; }":"=r"(a):"l"(p)); return a; }

DI void split2(float x, float y, uint32_t& hi, uint32_t& lo){
  __nv_bfloat16 hx = __float2bfloat16_rn(x), hy = __float2bfloat16_rn(y);
  float rx = x - __bfloat162float(hx), ry = y - __bfloat162float(hy);
  __nv_bfloat162 H; H.x = hx; H.y = hy;
  __nv_bfloat162 L2 = __floats2bfloat162_rn(rx, ry);
  hi = *reinterpret_cast<uint32_t*>(&H);
  lo = *reinterpret_cast<uint32_t*>(&L2);
}

DI void ldmx4(uint32_t* r, uint32_t addr){
  asm volatile("ldmatrix.sync.aligned.m8n8.x4.shared.b16 {%0,%1,%2,%3}, [%4];"
    : "=r"(r[0]),"=r"(r[1]),"=r"(r[2]),"=r"(r[3]) : "r"(addr));
}
DI void ldmx4t(uint32_t* r, uint32_t addr){
  asm volatile("ldmatrix.sync.aligned.m8n8.x4.trans.shared.b16 {%0,%1,%2,%3}, [%4];"
    : "=r"(r[0]),"=r"(r[1]),"=r"(r[2]),"=r"(r[3]) : "r"(addr));
}
DI void mma16816(float* c, const uint32_t* a, uint32_t b0, uint32_t b1){
  asm volatile("mma.sync.aligned.m16n8k16.row.col.f32.bf16.bf16.f32 "
    "{%0,%1,%2,%3}, {%4,%5,%6,%7}, {%8,%9}, {%0,%1,%2,%3};"
    : "+f"(c[0]),"+f"(c[1]),"+f"(c[2]),"+f"(c[3])
    : "r"(a[0]),"r"(a[1]),"r"(a[2]),"r"(a[3]), "r"(b0),"r"(b1));
}

__global__ void __launch_bounds__(NTHR, 2)
sdpa_mma_kernel(const float* __restrict__ q, const float* __restrict__ k,
                const float* __restrict__ v, const int* __restrict__ mask,
                float* __restrict__ out, float* __restrict__ attn)
{
    extern __shared__ char sm[];
    const uint32_t smb = smem_u32(sm);
    float* RED   = (float*)(sm + SM_RED);
    float* ILrow = (float*)(sm + SM_IL);

    const int tid  = threadIdx.x;
    const int wid  = tid >> 5, lane = tid & 31;
    const int wr   = wid >> 2, wc = wid & 3;    // 2 x 4 warp grid
    const int g    = lane >> 3, l7 = lane & 7;
    const int b    = blockIdx.x >> 5;
    const int q0   = (blockIdx.x & 31) * BM;

    // ---- stage Q (pre-scaled 1/8) as bf16 hi/lo ----
    const float* Qg = q + ((size_t)(b * L + q0)) * DDIM;
    #pragma unroll
    for (int j = 0; j < 4; ++j) {
        int id = tid + j * NTHR;              // 1024 float2
        int r = id >> 5, c = (id & 31) * 2;
        float2 x = *(const float2*)&Qg[r * DDIM + c];
        uint32_t hi, lo; split2(x.x * 0.125f, x.y * 0.125f, hi, lo);
        *(uint32_t*)(sm + SM_QHI + r * (SK*2) + c*2) = hi;
        *(uint32_t*)(sm + SM_QLO + r * (SK*2) + c*2) = lo;
    }
    __syncthreads();

    // ---- preload Q A-fragments ----
    uint32_t aH[4][4], aL[4][4];
    {
        int arow = wr*16 + l7 + (g & 1) * 8;
        int akoff = (g >> 1) * 8;
        #pragma unroll
        for (int ks = 0; ks < 4; ++ks) {
            uint32_t off = (uint32_t)(arow * SK + ks*16 + akoff) * 2;
            ldmx4(aH[ks], smb + SM_QHI + off);
            ldmx4(aL[ks], smb + SM_QLO + off);
        }
    }

    float lsumA = 0.f, lsumB = 0.f;
    const float* Kg = k + (size_t)b * L * DDIM;
    const float* Vg = v + (size_t)b * L * DDIM;
    const int rowA = wr * 16 + (lane >> 2);
    const int rowB = rowA + 8;
    const size_t grA = (size_t)(b*L + q0 + rowA) * L;
    const size_t grB = (size_t)(b*L + q0 + rowB) * L;
    float* Ab = attn + ((size_t)(b * L + q0)) * L;

    // O accumulator: warp's key-slice partial, 16 q-rows x 64 d
    float o[8][4];
    #pragma unroll
    for (int f = 0; f < 8; ++f)
        #pragma unroll
        for (int jj = 0; jj < 4; ++jj) o[f][jj] = 0.f;

    // prefetch K/V tile 0
    float4 kreg4[4], vreg4[4];
    #pragma unroll
    for (int j = 0; j < 4; ++j) {
        int id = tid + j * NTHR;              // 1024 float4
        int r = id >> 4, c = (id & 15) * 4;
        kreg4[j] = *(const float4*)&Kg[(size_t)r * DDIM + c];
        vreg4[j] = *(const float4*)&Vg[(size_t)r * DDIM + c];
    }

    // ============ fused loop, ONE barrier per tile (double-buffered K/V) ============
    #pragma unroll 1
    for (int kt = 0; kt < 16; ++kt) {
        const uint32_t buf = (uint32_t)(SM_KV + (kt & 1) * KVBUF);

        // stage K+V hi/lo into this tile's buffer
        #pragma unroll
        for (int j = 0; j < 4; ++j) {
            int id = tid + j * NTHR;
            int r = id >> 4, c = (id & 15) * 4;
            uint32_t off = buf + (uint32_t)(r * (SK*2) + c*2);
            uint32_t h0,l0,h1,l1;
            split2(kreg4[j].x, kreg4[j].y, h0, l0);
            split2(kreg4[j].z, kreg4[j].w, h1, l1);
            *(uint2*)(sm + off + KHI) = make_uint2(h0, h1);
            *(uint2*)(sm + off + KLO) = make_uint2(l0, l1);
            split2(vreg4[j].x, vreg4[j].y, h0, l0);
            split2(vreg4[j].z, vreg4[j].w, h1, l1);
            *(uint2*)(sm + off + VHI) = make_uint2(h0, h1);
            *(uint2*)(sm + off + VLO) = make_uint2(l0, l1);
        }
        __syncthreads();      // buffer complete; also fences reads of (kt-1)'s buffer

        // branch-free prefetch next tile (wraps; always in-bounds)
        {
            const int ktn = (kt + 1) & 15;
            const float* Kn = Kg + (size_t)ktn * 64 * DDIM;
            const float* Vn = Vg + (size_t)ktn * 64 * DDIM;
            #pragma unroll
            for (int j = 0; j < 4; ++j) {
                int id = tid + j * NTHR;
                int r = id >> 4, c = (id & 15) * 4;
                kreg4[j] = *(const float4*)&Kn[(size_t)r * DDIM + c];
                vreg4[j] = *(const float4*)&Vn[(size_t)r * DDIM + c];
            }
        }
        // this tile's mask loads (latency covered by GEMM1)
        int2 cmA[2], cmB[2];
        #pragma unroll
        for (int nf = 0; nf < 2; ++nf) {
            int col = kt*64 + wc*16 + nf*8 + (lane & 3)*2;
            cmA[nf] = *(const int2*)&mask[grA + col];
            cmB[nf] = *(const int2*)&mask[grB + col];
        }

        // ---- GEMM1: S slice = (Q/8) K^T ----
        float c4[2][4];
        #pragma unroll
        for (int i = 0; i < 2; ++i)
            #pragma unroll
            for (int jj = 0; jj < 4; ++jj) c4[i][jj] = 0.f;

        const int brow = wc*16 + l7 + (g >> 1) * 8;
        const int bkoff = (g & 1) * 8;
        #pragma unroll
        for (int ks = 0; ks < 4; ++ks) {
            uint32_t off = smb + buf + (uint32_t)(brow * SK + ks*16 + bkoff) * 2;
            uint32_t bh[4], bl[4];
            ldmx4(bh, off + KHI);
            ldmx4(bl, off + KLO);
            mma16816(c4[0], aH[ks], bh[0], bh[1]);
            mma16816(c4[0], aL[ks], bh[0], bh[1]);
            mma16816(c4[0], aH[ks], bl[0], bl[1]);
            mma16816(c4[1], aH[ks], bh[2], bh[3]);
            mma16816(c4[1], aL[ks], bh[2], bh[3]);
            mma16816(c4[1], aH[ks], bl[2], bl[3]);
        }

        // ---- epilogue: e = exp(masked s); write e to attn; pack e as PV A-frags ----
        uint32_t eH[4], eL[4];
        #pragma unroll
        for (int nf = 0; nf < 2; ++nf) {
            int col = kt*64 + wc*16 + nf*8 + (lane & 3)*2;
            float e0 = cmA[nf].x ? 0.f : __expf(c4[nf][0]);
            float e1 = cmA[nf].y ? 0.f : __expf(c4[nf][1]);
            float e2 = cmB[nf].x ? 0.f : __expf(c4[nf][2]);
            float e3 = cmB[nf].y ? 0.f : __expf(c4[nf][3]);
            lsumA += e0 + e1;
            lsumB += e2 + e3;
            *(float2*)&attn[grA + col] = make_float2(e0, e1);
            *(float2*)&attn[grB + col] = make_float2(e2, e3);
            split2(e0, e1, eH[nf*2 + 0], eL[nf*2 + 0]);
            split2(e2, e3, eH[nf*2 + 1], eL[nf*2 + 1]);
        }

        // ---- GEMM2: O += e_slice * V_slice ----
        const int vrow = l7 + (g & 1) * 8, vnoff = (g >> 1) * 8;
        #pragma unroll
        for (int nb = 0; nb < 4; ++nb) {
            uint32_t boff = smb + buf + (uint32_t)((wc*16 + vrow) * SK + nb*16 + vnoff) * 2;
            uint32_t vh[4], vl[4];
            ldmx4t(vh, boff + VHI);
            ldmx4t(vl, boff + VLO);
            mma16816(o[2*nb],   eH, vh[0], vh[1]);
            mma16816(o[2*nb],   eL, vh[0], vh[1]);
            mma16816(o[2*nb],   eH, vl[0], vl[1]);
            mma16816(o[2*nb+1], eH, vh[2], vh[3]);
            mma16816(o[2*nb+1], eL, vh[2], vh[3]);
            mma16816(o[2*nb+1], eH, vl[2], vl[3]);
        }
        // no trailing barrier: next tile's STS targets the other buffer
    }

    // ---- row-sum partials (RED is outside the K/V region: safe pre-barrier) ----
    lsumA += __shfl_xor_sync(0xffffffffu, lsumA, 1);
    lsumA += __shfl_xor_sync(0xffffffffu, lsumA, 2);
    lsumB += __shfl_xor_sync(0xffffffffu, lsumB, 1);
    lsumB += __shfl_xor_sync(0xffffffffu, lsumB, 2);
    if ((lane & 3) == 0) {
        RED[rowA*4 + wc] = lsumA;
        RED[rowB*4 + wc] = lsumB;
    }
    __syncthreads();          // all warps done with K/V buffers + RED complete

    // ---- O partials to smem (overlays dead K/V region) ----
    {
        float* OPw = (float*)(sm + SM_OP) + wid * 16 * 64;
        int r0 = lane >> 2;
        #pragma unroll
        for (int f = 0; f < 8; ++f) {
            int c = f*8 + (lane & 3)*2;
            *(float2*)&OPw[r0*64 + c]      = make_float2(o[f][0], o[f][1]);
            *(float2*)&OPw[(r0+8)*64 + c]  = make_float2(o[f][2], o[f][3]);
        }
    }
    if (tid < 32) {
        float s4 = RED[tid*4] + RED[tid*4+1] + RED[tid*4+2] + RED[tid*4+3];
        ILrow[tid] = 1.f / s4;
    }
    __syncthreads();

    // ---- finalize O: sum 4 key-slice partials, scale by 1/l ----
    {
        int r = tid >> 3, cg = (tid & 7) * 8;
        float il = ILrow[r];
        const float* OP = (const float*)(sm + SM_OP);
        float a0=0,a1=0,a2=0,a3=0,a4=0,a5=0,a6=0,a7=0;
        #pragma unroll
        for (int wcx = 0; wcx < 4; ++wcx) {
            int base = (((r >> 4)*4 + wcx)*16 + (r & 15))*64 + cg;
            float4 u0 = *(const float4*)&OP[base];
            float4 u1 = *(const float4*)&OP[base + 4];
            a0 += u0.x; a1 += u0.y; a2 += u0.z; a3 += u0.w;
            a4 += u1.x; a5 += u1.y; a6 += u1.z; a7 += u1.w;
        }
        float* orow = out + ((size_t)(b*L + q0 + r)) * DDIM + cg;
        *(float4*)&orow[0] = make_float4(a0*il, a1*il, a2*il, a3*il);
        *(float4*)&orow[4] = make_float4(a4*il, a5*il, a6*il, a7*il);
    }

    // ---- streaming attn rescale: p = e * il ----
    #pragma unroll 4
    for (int j = 0; j < 32; ++j) {
        int id = tid + j * NTHR;             // 8192 float4 over 32x1024
        int r = id >> 8, ci = (id & 255) * 4;
        float il = ILrow[r];
        float4 t = *(const float4*)&Ab[(size_t)r * L + ci];
        t.x *= il; t.y *= il; t.z *= il; t.w *= il;
        *(float4*)&Ab[(size_t)r * L + ci] = t;
    }
}

extern "C" void kernel_launch(void* const* d_in, const int* in_sizes, int n_in,
                              void* d_out, int out_size)
{
    (void)in_sizes; (void)n_in; (void)out_size;
    const float* q = (const float*)d_in[0];
    const float* k = (const float*)d_in[1];
    const float* v = (const float*)d_in[2];
    const int*   mask = (const int*)d_in[3];

    float* outp = (float*)d_out;                            // [B, LQ, DD]
    float* attn = outp + (size_t)BATCH * L * DDIM;          // [B, LQ, LK]

    cudaFuncSetAttribute(sdpa_mma_kernel,
                         cudaFuncAttributeMaxDynamicSharedMemorySize, SM_TOT);

    dim3 grid(BATCH * (L / BM));    // 2048
    sdpa_mma_kernel<<<grid, NTHR, SM_TOT>>>(q, k, v, mask, outp, attn);
}

// round 17
// speedup vs baseline: 1.5072x; 1.1164x over previous
#include <cuda_runtime.h>
#include <cuda_bf16.h>
#include <cstdint>
#include <math.h>

#define DI __device__ __forceinline__

#define BATCH 64
#define L     1024
#define DDIM  64
#define BM    32
#define NTHR  256
#define SK    72            // smem row stride (halves)

// smem byte offsets — 83584 B total => 2 CTAs/SM
#define SM_QHI  0           // 32*144 = 4608
#define SM_QLO  4608
#define SM_KV   9216        // 2 buffers x 36864 (KHI/KLO/VHI/VLO @ 0/9216/18432/27648)
#define KVBUF   36864
#define SM_OP   9216        // reused AFTER loop (+sync): 8 warps x 16 x 64 floats
#define SM_RED  82944       // float[32][4]
#define SM_IL   83456       // float[32]
#define SM_TOT  83584

// precomputed bf16 hi/lo K and V (8 MB each)
__device__ __nv_bfloat16 g_khi[BATCH * L * DDIM];
__device__ __nv_bfloat16 g_klo[BATCH * L * DDIM];
__device__ __nv_bfloat16 g_vhi[BATCH * L * DDIM];
__device__ __nv_bfloat16 g_vlo[BATCH * L * DDIM];

DI uint32_t smem_u32(const void* p){ uint32_t a;
  asm("{ .reg .u64 t; cvta.to.shared.u64 t, %1; cvt.u32.u64 %0, t; }":"=r"(a):"l"(p)); return a; }

DI void split2(float x, float y, uint32_t& hi, uint32_t& lo){
  __nv_bfloat16 hx = __float2bfloat16_rn(x), hy = __float2bfloat16_rn(y);
  float rx = x - __bfloat162float(hx), ry = y - __bfloat162float(hy);
  __nv_bfloat162 H; H.x = hx; H.y = hy;
  __nv_bfloat162 L2 = __floats2bfloat162_rn(rx, ry);
  hi = *reinterpret_cast<uint32_t*>(&H);
  lo = *reinterpret_cast<uint32_t*>(&L2);
}

DI void ldmx4(uint32_t* r, uint32_t addr){
  asm volatile("ldmatrix.sync.aligned.m8n8.x4.shared.b16 {%0,%1,%2,%3}, [%4];"
    : "=r"(r[0]),"=r"(r[1]),"=r"(r[2]),"=r"(r[3]) : "r"(addr));
}
DI void ldmx4t(uint32_t* r, uint32_t addr){
  asm volatile("ldmatrix.sync.aligned.m8n8.x4.trans.shared.b16 {%0,%1,%2,%3}, [%4];"
    : "=r"(r[0]),"=r"(r[1]),"=r"(r[2]),"=r"(r[3]) : "r"(addr));
}
DI void mma16816(float* c, const uint32_t* a, uint32_t b0, uint32_t b1){
  asm volatile("mma.sync.aligned.m16n8k16.row.col.f32.bf16.bf16.f32 "
    "{%0,%1,%2,%3}, {%4,%5,%6,%7}, {%8,%9}, {%0,%1,%2,%3};"
    : "+f"(c[0]),"+f"(c[1]),"+f"(c[2]),"+f"(c[3])
    : "r"(a[0]),"r"(a[1]),"r"(a[2]),"r"(a[3]), "r"(b0),"r"(b1));
}
DI void cpasync16(uint32_t saddr, const void* gptr){
  asm volatile("cp.async.ca.shared.global [%0], [%1], 16;"
    :: "r"(saddr), "l"(gptr) : "memory");
}
#define CP_COMMIT() asm volatile("cp.async.commit_group;":::"memory")
#define CP_WAIT0()  asm volatile("cp.async.wait_group 0;":::"memory")

// ---------------- precompute: K,V fp32 -> bf16 hi/lo ----------------
__global__ void __launch_bounds__(256)
convert_kv_kernel(const float* __restrict__ k, const float* __restrict__ v)
{
    size_t i = ((size_t)blockIdx.x * 256 + threadIdx.x) * 4;   // 4 elems/thread
    float4 kx = *(const float4*)&k[i];
    float4 vx = *(const float4*)&v[i];
    uint32_t h0,l0,h1,l1;
    split2(kx.x, kx.y, h0, l0);
    split2(kx.z, kx.w, h1, l1);
    *(uint2*)&g_khi[i] = make_uint2(h0, h1);
    *(uint2*)&g_klo[i] = make_uint2(l0, l1);
    split2(vx.x, vx.y, h0, l0);
    split2(vx.z, vx.w, h1, l1);
    *(uint2*)&g_vhi[i] = make_uint2(h0, h1);
    *(uint2*)&g_vlo[i] = make_uint2(l0, l1);
}

// ---------------- main fused kernel ----------------
__global__ void __launch_bounds__(NTHR, 2)
sdpa_mma_kernel(const float* __restrict__ q, const int* __restrict__ mask,
                float* __restrict__ out, float* __restrict__ attn)
{
    extern __shared__ char sm[];
    const uint32_t smb = smem_u32(sm);
    float* RED   = (float*)(sm + SM_RED);
    float* ILrow = (float*)(sm + SM_IL);

    const int tid  = threadIdx.x;
    const int wid  = tid >> 5, lane = tid & 31;
    const int wr   = wid >> 2, wc = wid & 3;    // 2 x 4 warp grid
    const int g    = lane >> 3, l7 = lane & 7;
    const int b    = blockIdx.x >> 5;
    const int q0   = (blockIdx.x & 31) * BM;

    // ---- stage Q (pre-scaled 1/8) as bf16 hi/lo ----
    const float* Qg = q + ((size_t)(b * L + q0)) * DDIM;
    #pragma unroll
    for (int j = 0; j < 4; ++j) {
        int id = tid + j * NTHR;              // 1024 float2
        int r = id >> 5, c = (id & 31) * 2;
        float2 x = *(const float2*)&Qg[r * DDIM + c];
        uint32_t hi, lo; split2(x.x * 0.125f, x.y * 0.125f, hi, lo);
        *(uint32_t*)(sm + SM_QHI + r * (SK*2) + c*2) = hi;
        *(uint32_t*)(sm + SM_QLO + r * (SK*2) + c*2) = lo;
    }
    __syncthreads();

    // ---- preload Q A-fragments ----
    uint32_t aH[4][4], aL[4][4];
    {
        int arow = wr*16 + l7 + (g & 1) * 8;
        int akoff = (g >> 1) * 8;
        #pragma unroll
        for (int ks = 0; ks < 4; ++ks) {
            uint32_t off = (uint32_t)(arow * SK + ks*16 + akoff) * 2;
            ldmx4(aH[ks], smb + SM_QHI + off);
            ldmx4(aL[ks], smb + SM_QLO + off);
        }
    }

    float lsumA = 0.f, lsumB = 0.f;
    const int rowA = wr * 16 + (lane >> 2);
    const int rowB = rowA + 8;
    const size_t grA = (size_t)(b*L + q0 + rowA) * L;
    const size_t grB = (size_t)(b*L + q0 + rowB) * L;
    float* Ab = attn + ((size_t)(b * L + q0)) * L;

    // O accumulator: warp's key-slice partial, 16 q x 64 d
    float o[8][4];
    #pragma unroll
    for (int f = 0; f < 8; ++f)
        #pragma unroll
        for (int jj = 0; jj < 4; ++jj) o[f][jj] = 0.f;

    const __nv_bfloat16* bases[4] = {g_khi, g_klo, g_vhi, g_vlo};
    const int sr = tid >> 3;              // staging row within 64 (per 512-chunk set)
    const int sc = tid & 7;               // 16B chunk within row

    // prologue: issue tile 0 into buffer 0
    #pragma unroll
    for (int a = 0; a < 4; ++a) {
        #pragma unroll
        for (int jj = 0; jj < 2; ++jj) {
            int r = sr + jj * 32;
            uint32_t soff = smb + SM_KV + (uint32_t)(a*9216 + r*144 + sc*16);
            cpasync16(soff, bases[a] + ((size_t)b * L + r) * DDIM + sc*8);
        }
    }
    CP_COMMIT();

    // ============ fused loop: cp.async double buffer, one barrier/tile ============
    #pragma unroll 1
    for (int kt = 0; kt < 16; ++kt) {
        const uint32_t buf = (uint32_t)(SM_KV + (kt & 1) * KVBUF);
        CP_WAIT0();
        __syncthreads();      // tile kt ready everywhere; all reads of other buf done

        // issue next tile into other buffer (wraps; always in-bounds)
        {
            const int ktn = (kt + 1) & 15;
            const uint32_t nbuf = (uint32_t)(SM_KV + (ktn & 1) * KVBUF);
            #pragma unroll
            for (int a = 0; a < 4; ++a) {
                #pragma unroll
                for (int jj = 0; jj < 2; ++jj) {
                    int r = sr + jj * 32;
                    uint32_t soff = smb + nbuf + (uint32_t)(a*9216 + r*144 + sc*16);
                    cpasync16(soff, bases[a] + ((size_t)b * L + ktn*64 + r) * DDIM + sc*8);
                }
            }
            CP_COMMIT();
        }
        // this tile's mask loads (latency covered by GEMM1)
        int2 cmA[2], cmB[2];
        #pragma unroll
        for (int nf = 0; nf < 2; ++nf) {
            int col = kt*64 + wc*16 + nf*8 + (lane & 3)*2;
            cmA[nf] = *(const int2*)&mask[grA + col];
            cmB[nf] = *(const int2*)&mask[grB + col];
        }

        // ---- GEMM1: S slice = (Q/8) K^T ----
        float c4[2][4];
        #pragma unroll
        for (int i = 0; i < 2; ++i)
            #pragma unroll
            for (int jj = 0; jj < 4; ++jj) c4[i][jj] = 0.f;

        const int brow = wc*16 + l7 + (g >> 1) * 8;
        const int bkoff = (g & 1) * 8;
        #pragma unroll
        for (int ks = 0; ks < 4; ++ks) {
            uint32_t off = smb + buf + (uint32_t)(brow * SK + ks*16 + bkoff) * 2;
            uint32_t bh[4], bl[4];
            ldmx4(bh, off);               // KHI @ +0
            ldmx4(bl, off + 9216);        // KLO
            mma16816(c4[0], aH[ks], bh[0], bh[1]);
            mma16816(c4[0], aL[ks], bh[0], bh[1]);
            mma16816(c4[0], aH[ks], bl[0], bl[1]);
            mma16816(c4[1], aH[ks], bh[2], bh[3]);
            mma16816(c4[1], aL[ks], bh[2], bh[3]);
            mma16816(c4[1], aH[ks], bl[2], bl[3]);
        }

        // ---- epilogue: e = exp(masked s); write e to attn; pack e as PV A-frags ----
        uint32_t eH[4], eL[4];
        #pragma unroll
        for (int nf = 0; nf < 2; ++nf) {
            int col = kt*64 + wc*16 + nf*8 + (lane & 3)*2;
            float e0 = cmA[nf].x ? 0.f : __expf(c4[nf][0]);
            float e1 = cmA[nf].y ? 0.f : __expf(c4[nf][1]);
            float e2 = cmB[nf].x ? 0.f : __expf(c4[nf][2]);
            float e3 = cmB[nf].y ? 0.f : __expf(c4[nf][3]);
            lsumA += e0 + e1;
            lsumB += e2 + e3;
            *(float2*)&attn[grA + col] = make_float2(e0, e1);
            *(float2*)&attn[grB + col] = make_float2(e2, e3);
            split2(e0, e1, eH[nf*2 + 0], eL[nf*2 + 0]);
            split2(e2, e3, eH[nf*2 + 1], eL[nf*2 + 1]);
        }

        // ---- GEMM2: O += e_slice * V_slice ----
        const int vrow = l7 + (g & 1) * 8, vnoff = (g >> 1) * 8;
        #pragma unroll
        for (int nb = 0; nb < 4; ++nb) {
            uint32_t boff = smb + buf + (uint32_t)((wc*16 + vrow) * SK + nb*16 + vnoff) * 2;
            uint32_t vh[4], vl[4];
            ldmx4t(vh, boff + 18432);     // VHI
            ldmx4t(vl, boff + 27648);     // VLO
            mma16816(o[2*nb],   eH, vh[0], vh[1]);
            mma16816(o[2*nb],   eL, vh[0], vh[1]);
            mma16816(o[2*nb],   eH, vl[0], vl[1]);
            mma16816(o[2*nb+1], eH, vh[2], vh[3]);
            mma16816(o[2*nb+1], eL, vh[2], vh[3]);
            mma16816(o[2*nb+1], eH, vl[2], vl[3]);
        }
    }

    // ---- row-sum partials ----
    lsumA += __shfl_xor_sync(0xffffffffu, lsumA, 1);
    lsumA += __shfl_xor_sync(0xffffffffu, lsumA, 2);
    lsumB += __shfl_xor_sync(0xffffffffu, lsumB, 1);
    lsumB += __shfl_xor_sync(0xffffffffu, lsumB, 2);
    if ((lane & 3) == 0) {
        RED[rowA*4 + wc] = lsumA;
        RED[rowB*4 + wc] = lsumB;
    }
    __syncthreads();          // all warps done with K/V buffers + RED complete

    // ---- O partials to smem (overlays dead K/V region) ----
    {
        float* OPw = (float*)(sm + SM_OP) + wid * 16 * 64;
        int r0 = lane >> 2;
        #pragma unroll
        for (int f = 0; f < 8; ++f) {
            int c = f*8 + (lane & 3)*2;
            *(float2*)&OPw[r0*64 + c]      = make_float2(o[f][0], o[f][1]);
            *(float2*)&OPw[(r0+8)*64 + c]  = make_float2(o[f][2], o[f][3]);
        }
    }
    if (tid < 32) {
        float s4 = RED[tid*4] + RED[tid*4+1] + RED[tid*4+2] + RED[tid*4+3];
        ILrow[tid] = 1.f / s4;
    }
    __syncthreads();

    // ---- finalize O: sum 4 key-slice partials, scale by 1/l ----
    {
        int r = tid >> 3, cg = (tid & 7) * 8;
        float il = ILrow[r];
        const float* OP = (const float*)(sm + SM_OP);
        float a0=0,a1=0,a2=0,a3=0,a4=0,a5=0,a6=0,a7=0;
        #pragma unroll
        for (int wcx = 0; wcx < 4; ++wcx) {
            int base = (((r >> 4)*4 + wcx)*16 + (r & 15))*64 + cg;
            float4 u0 = *(const float4*)&OP[base];
            float4 u1 = *(const float4*)&OP[base + 4];
            a0 += u0.x; a1 += u0.y; a2 += u0.z; a3 += u0.w;
            a4 += u1.x; a5 += u1.y; a6 += u1.z; a7 += u1.w;
        }
        float* orow = out + ((size_t)(b*L + q0 + r)) * DDIM + cg;
        *(float4*)&orow[0] = make_float4(a0*il, a1*il, a2*il, a3*il);
        *(float4*)&orow[4] = make_float4(a4*il, a5*il, a6*il, a7*il);
    }

    // ---- streaming attn rescale: p = e * il ----
    #pragma unroll 4
    for (int j = 0; j < 32; ++j) {
        int id = tid + j * NTHR;             // 8192 float4 over 32x1024
        int r = id >> 8, ci = (id & 255) * 4;
        float il = ILrow[r];
        float4 t = *(const float4*)&Ab[(size_t)r * L + ci];
        t.x *= il; t.y *= il; t.z *= il; t.w *= il;
        *(float4*)&Ab[(size_t)r * L + ci] = t;
    }
}

extern "C" void kernel_launch(void* const* d_in, const int* in_sizes, int n_in,
                              void* d_out, int out_size)
{
    (void)in_sizes; (void)n_in; (void)out_size;
    const float* q = (const float*)d_in[0];
    const float* k = (const float*)d_in[1];
    const float* v = (const float*)d_in[2];
    const int*   mask = (const int*)d_in[3];

    float* outp = (float*)d_out;                            // [B, LQ, DD]
    float* attn = outp + (size_t)BATCH * L * DDIM;          // [B, LQ, LK]

    cudaFuncSetAttribute(sdpa_mma_kernel,
                         cudaFuncAttributeMaxDynamicSharedMemorySize, SM_TOT);

    // 1) convert K/V to bf16 hi/lo once
    convert_kv_kernel<<<(BATCH * L * DDIM) / (256 * 4), 256>>>(k, v);
    // 2) fused attention
    dim3 grid(BATCH * (L / BM));    // 2048
    sdpa_mma_kernel<<<grid, NTHR, SM_TOT>>>(q, mask, outp, attn);
}